// round 1
// baseline (speedup 1.0000x reference)
#include <cuda_runtime.h>
#include <math.h>

// Problem constants
#define B_    64
#define CIN   16
#define HH    256
#define WW    256
#define COUT  64
#define OH    254
#define OW    254

// Tiling
#define TH     16      // output rows per CTA
#define TW     96      // output cols per CTA
#define PX     6       // pixels per thread along W
#define SROWS  18      // TH + 2 halo
#define SCOLS  98      // TW + 2 halo
#define SPITCH 100     // padded smem row pitch (floats), even -> 8B aligned rows

#define SMEM_IN_FLOATS   (CIN * SROWS * SPITCH)          // 28800 floats = 115200 B
#define SMEM_W_PAIRS     (COUT * CIN * 9)                // 9216 u64 pairs = 73728 B
#define SMEM_BYTES       (SMEM_IN_FLOATS * 4 + SMEM_W_PAIRS * 8 + COUT * 4)  // 189184 B

typedef unsigned long long u64;

__device__ __forceinline__ u64 pk2(float lo, float hi) {
    u64 r;
    asm("mov.b64 %0, {%1, %2};" : "=l"(r) : "f"(lo), "f"(hi));
    return r;
}
__device__ __forceinline__ float2 upk2(u64 v) {
    float2 f;
    asm("mov.b64 {%0, %1}, %2;" : "=f"(f.x), "=f"(f.y) : "l"(v));
    return f;
}
// Blackwell packed dual fp32 FMA (SASS: FFMA2). Only reachable via PTX.
__device__ __forceinline__ u64 ffma2(u64 a, u64 b, u64 c) {
    u64 d;
    asm("fma.rn.f32x2 %0, %1, %2, %3;" : "=l"(d) : "l"(a), "l"(b), "l"(c));
    return d;
}

extern __shared__ float smem[];

__global__ __launch_bounds__(256, 1)
void conv_min_tanh_kernel(const float* __restrict__ x,
                          const float* __restrict__ w,
                          const float* __restrict__ bias,
                          float* __restrict__ out)
{
    float* sIn = smem;                               // [CIN][SROWS][SPITCH]
    u64*   sW  = (u64*)(smem + SMEM_IN_FLOATS);      // [COUT][CIN][9] duplicated (w,w) pairs
    float* sB  = (float*)(sW + SMEM_W_PAIRS);        // [COUT]

    const int tx  = threadIdx.x;        // 0..15
    const int ty  = threadIdx.y;        // 0..15
    const int tid = ty * 16 + tx;

    const int tileX = blockIdx.x * TW;
    const int tileY = blockIdx.y * TH;
    const int b     = blockIdx.z;

    // ---- Load weights as duplicated f32x2 pairs (broadcast-friendly LDS.64 later) ----
    for (int i = tid; i < COUT * CIN * 9; i += 256) {
        float v = w[i];
        sW[i] = pk2(v, v);
    }
    if (tid < COUT) sB[tid] = bias[tid];

    // ---- Load input tile (all 16 input channels, with halo, zero-padded OOB) ----
    const float* xb = x + (size_t)b * (CIN * HH * WW);
    for (int i = tid; i < CIN * SROWS * SCOLS; i += 256) {
        int ci  = i / (SROWS * SCOLS);
        int rem = i - ci * (SROWS * SCOLS);
        int r   = rem / SCOLS;
        int c   = rem - r * SCOLS;
        int iy  = tileY + r;
        int ix  = tileX + c;
        float v = 0.0f;
        if (iy < HH && ix < WW)
            v = xb[ci * (HH * WW) + iy * WW + ix];
        sIn[ci * (SROWS * SPITCH) + r * SPITCH + c] = v;
    }
    __syncthreads();

    // ---- Compute: 6 pixels/thread, 8-cout register blocking, f32x2 packed FMA ----
    float mn[PX];
    #pragma unroll
    for (int p = 0; p < PX; p++) mn[p] = __int_as_float(0x7f800000);  // +inf

    #pragma unroll 1
    for (int cb = 0; cb < COUT; cb += 8) {
        u64 acc[8][3];
        #pragma unroll
        for (int co = 0; co < 8; co++) {
            float bv = sB[cb + co];
            u64 bb = pk2(bv, bv);
            acc[co][0] = bb; acc[co][1] = bb; acc[co][2] = bb;
        }

        #pragma unroll 1
        for (int ci = 0; ci < CIN; ci++) {
            #pragma unroll
            for (int ky = 0; ky < 3; ky++) {
                // 8 consecutive input floats as 4 aligned u64 (24*tx bytes: 8B aligned, conflict-free)
                const u64* rp = (const u64*)(sIn + ci * (SROWS * SPITCH)
                                                 + (ty + ky) * SPITCH + tx * PX);
                u64 a0 = rp[0], a1 = rp[1], a2 = rp[2], a3 = rp[3];
                float2 f0 = upk2(a0), f1 = upk2(a1), f2 = upk2(a2), f3 = upk2(a3);
                u64 t0 = pk2(f0.y, f1.x);   // shifted pairs for middle tap
                u64 t1 = pk2(f1.y, f2.x);
                u64 t2 = pk2(f2.y, f3.x);

                const u64* wp = sW + ((cb * CIN + ci) * 9) + ky * 3;
                #pragma unroll
                for (int co = 0; co < 8; co++) {
                    u64 w0 = wp[0], w1 = wp[1], w2 = wp[2];   // uniform -> LDS broadcast
                    acc[co][0] = ffma2(w0, a0, acc[co][0]);
                    acc[co][0] = ffma2(w1, t0, acc[co][0]);
                    acc[co][0] = ffma2(w2, a1, acc[co][0]);
                    acc[co][1] = ffma2(w0, a1, acc[co][1]);
                    acc[co][1] = ffma2(w1, t1, acc[co][1]);
                    acc[co][1] = ffma2(w2, a2, acc[co][1]);
                    acc[co][2] = ffma2(w0, a2, acc[co][2]);
                    acc[co][2] = ffma2(w1, t2, acc[co][2]);
                    acc[co][2] = ffma2(w2, a3, acc[co][2]);
                    wp += CIN * 9;   // advance to next cout
                }
            }
        }

        #pragma unroll
        for (int co = 0; co < 8; co++) {
            #pragma unroll
            for (int j = 0; j < 3; j++) {
                float2 v = upk2(acc[co][j]);
                mn[2 * j]     = fminf(mn[2 * j],     v.x);
                mn[2 * j + 1] = fminf(mn[2 * j + 1], v.y);
            }
        }
    }

    // ---- Epilogue: double tanh + guarded store ----
    const int oy = tileY + ty;
    if (oy < OH) {
        const int oxb = tileX + tx * PX;
        float* op = out + ((size_t)b * OH + oy) * OW;
        #pragma unroll
        for (int p = 0; p < PX; p++) {
            int ox = oxb + p;
            if (ox < OW) op[ox] = tanhf(tanhf(mn[p]));
        }
    }
}

extern "C" void kernel_launch(void* const* d_in, const int* in_sizes, int n_in,
                              void* d_out, int out_size)
{
    const float* x    = (const float*)d_in[0];   // [64,16,256,256]
    const float* w    = (const float*)d_in[1];   // [64,16,3,3]
    const float* bias = (const float*)d_in[2];   // [64]
    float* out = (float*)d_out;                  // [64,1,254,254]

    // Host-side attribute set; idempotent, not a stream op (graph-capture safe).
    cudaFuncSetAttribute(conv_min_tanh_kernel,
                         cudaFuncAttributeMaxDynamicSharedMemorySize, SMEM_BYTES);

    dim3 grid((OW + TW - 1) / TW,   // 3
              (OH + TH - 1) / TH,   // 16
              B_);                  // 64
    dim3 block(16, 16);
    conv_min_tanh_kernel<<<grid, block, SMEM_BYTES>>>(x, w, bias, out);
}